// round 3
// baseline (speedup 1.0000x reference)
#include <cuda_runtime.h>
#include <cstdint>

#define N_NODES 100000
#define N_EDGES 3200000
#define N_FEAT  24
#define LAYERS  6

// Scratch (allocation-free rule: __device__ globals).
// __align__(16): buffers are accessed as float4 (LDG.128/STG.128/RED.128).
__device__ __align__(16) float g_bufA[(size_t)N_NODES * N_FEAT];
__device__ __align__(16) float g_bufB[(size_t)N_NODES * N_FEAT];
__device__ __align__(16) int   g_row[N_EDGES];
__device__ __align__(16) int   g_col[N_EDGES];
__device__ int g_flag;  // 0 = indices are int64, 1 = indices are int32

// ---------------------------------------------------------------------------
// Index dtype detection. JAX with default x64-disabled silently downcasts the
// reference's int64 indices to int32, so the real device buffers may be either
// width. Reading N_EDGES int32 words is in-bounds under BOTH interpretations
// (whole int32 buffer, or first half of an int64 buffer). For little-endian
// int64 values in [0, 100000) every odd (high) word is zero; any nonzero odd
// word proves int32.
// ---------------------------------------------------------------------------
__global__ void reset_flag_kernel() { g_flag = 0; }

__global__ void probe_dtype_kernel(const int* __restrict__ p32) {
    int i = blockIdx.x * blockDim.x + threadIdx.x;
    int w = 2 * i + 1;                 // odd word
    if (w < N_EDGES && p32[w] != 0) atomicExch(&g_flag, 1);
}

// ---------------------------------------------------------------------------
// Convert indices to int32 scratch (once per launch), branching on detected
// dtype; clamp as a fault guard (misdetection -> visible rel_err, not a trap).
// ---------------------------------------------------------------------------
__global__ void convert_idx_kernel(const void* __restrict__ rptr,
                                   const void* __restrict__ cptr) {
    int e = blockIdx.x * blockDim.x + threadIdx.x;
    if (e >= N_EDGES) return;
    int r, c;
    if (g_flag == 1) {  // int32
        r = ((const int*)rptr)[e];
        c = ((const int*)cptr)[e];
    } else {            // int64
        r = (int)((const long long*)rptr)[e];
        c = (int)((const long long*)cptr)[e];
    }
    r = min(max(r, 0), N_NODES - 1);
    c = min(max(c, 0), N_NODES - 1);
    g_row[e] = r;
    g_col[e] = c;
}

// ---------------------------------------------------------------------------
// Zero a buffer (float4 granularity; N_NODES*N_FEAT = 2.4M floats = 600K f4).
// ---------------------------------------------------------------------------
__global__ void zero_kernel(float4* __restrict__ p, int n4) {
    int i = blockIdx.x * blockDim.x + threadIdx.x;
    if (i < n4) p[i] = make_float4(0.f, 0.f, 0.f, 0.f);
}

// Vectorized fp32 reduction (sm_90+): 1 instruction per 16B instead of 4
// scalar atomicAdds.
__device__ __forceinline__ void red_add_v4(float4* addr, float4 v) {
    asm volatile("red.global.add.v4.f32 [%0], {%1, %2, %3, %4};"
                 :: "l"(addr), "f"(v.x), "f"(v.y), "f"(v.z), "f"(v.w)
                 : "memory");
}

// ---------------------------------------------------------------------------
// Edge-parallel COO SpMM scatter: dst[row[e]] += vals[e] * src[col[e]].
// One thread per edge; 6x LDG.128 gather (L2-resident src), 6x RED.128.
// ---------------------------------------------------------------------------
__global__ void __launch_bounds__(256)
spmm_scatter_kernel(const float* __restrict__ vals,
                    const float* __restrict__ src,
                    float* __restrict__ dst) {
    int e = blockIdx.x * blockDim.x + threadIdx.x;
    if (e >= N_EDGES) return;

    float v = vals[e];
    int   r = g_row[e];
    int   c = g_col[e];

    const float4* __restrict__ xs = (const float4*)(src + (size_t)c * N_FEAT);
    float4* od = (float4*)(dst + (size_t)r * N_FEAT);

    // 6 independent 16B loads -> good MLP against L2 latency.
    float4 a0 = xs[0], a1 = xs[1], a2 = xs[2], a3 = xs[3], a4 = xs[4], a5 = xs[5];

    a0.x *= v; a0.y *= v; a0.z *= v; a0.w *= v;
    a1.x *= v; a1.y *= v; a1.z *= v; a1.w *= v;
    a2.x *= v; a2.y *= v; a2.z *= v; a2.w *= v;
    a3.x *= v; a3.y *= v; a3.z *= v; a3.w *= v;
    a4.x *= v; a4.y *= v; a4.z *= v; a4.w *= v;
    a5.x *= v; a5.y *= v; a5.z *= v; a5.w *= v;

    red_add_v4(od + 0, a0);
    red_add_v4(od + 1, a1);
    red_add_v4(od + 2, a2);
    red_add_v4(od + 3, a3);
    red_add_v4(od + 4, a4);
    red_add_v4(od + 5, a5);
}

// ---------------------------------------------------------------------------
// kernel_launch: detect index dtype, convert once, then 6 x (zero; scatter),
// ping-ponging between device buffers. Default stream only, no syncs, no
// allocations -> graph-capturable.
// ---------------------------------------------------------------------------
extern "C" void kernel_launch(void* const* d_in, const int* in_sizes, int n_in,
                              void* d_out, int out_size) {
    const float* x    = (const float*)d_in[0];  // [N_NODES, N_FEAT]
    const float* vals = (const float*)d_in[1];  // [N_EDGES]
    const void*  rraw = d_in[2];                // [N_EDGES] int32 or int64
    const void*  craw = d_in[3];                // [N_EDGES] int32 or int64
    float* out = (float*)d_out;                 // [N_NODES, N_FEAT]

    float* bufA;
    float* bufB;
    cudaGetSymbolAddress((void**)&bufA, g_bufA);
    cudaGetSymbolAddress((void**)&bufB, g_bufB);

    const int threads = 256;
    const int eblocks = (N_EDGES + threads - 1) / threads;
    const int pblocks = (N_EDGES / 2 + threads - 1) / threads;
    const int n4      = (N_NODES * N_FEAT) / 4;  // 600000
    const int zblocks = (n4 + threads - 1) / threads;

    reset_flag_kernel<<<1, 1>>>();
    probe_dtype_kernel<<<pblocks, threads>>>((const int*)rraw);
    convert_idx_kernel<<<eblocks, threads>>>(rraw, craw);

    // Layer chain: x -> A -> B -> A -> B -> A -> out
    const float* src[LAYERS] = { x, bufA, bufB, bufA, bufB, bufA };
    float*       dst[LAYERS] = { bufA, bufB, bufA, bufB, bufA, out };

    for (int l = 0; l < LAYERS; l++) {
        zero_kernel<<<zblocks, threads>>>((float4*)dst[l], n4);
        spmm_scatter_kernel<<<eblocks, threads>>>(vals, src[l], dst[l]);
    }
}

// round 4
// speedup vs baseline: 1.1941x; 1.1941x over previous
#include <cuda_runtime.h>
#include <cstdint>

#define N_NODES 100000
#define N_EDGES 3200000
#define N_FEAT  24
#define LAYERS  6

// ---------------------------------------------------------------------------
// Scratch (allocation-free rule: __device__ globals).
// ---------------------------------------------------------------------------
__device__ __align__(16) float g_bufA[(size_t)N_NODES * N_FEAT];
__device__ __align__(16) float g_bufB[(size_t)N_NODES * N_FEAT];
__device__ __align__(16) int   g_row[N_EDGES];
__device__ __align__(16) int   g_col[N_EDGES];
__device__ float2 g_edge[N_EDGES];          // CSR payload: (val, col-as-bits), row-sorted
__device__ int    g_cnt[N_NODES];           // per-row degree histogram
__device__ int    g_rowptr[N_NODES + 1];    // exclusive prefix of g_cnt
__device__ int    g_cursor[N_NODES];        // placement cursors
__device__ int    g_flag;                   // 0 = int64 indices, 1 = int32

// ---------------------------------------------------------------------------
// Index dtype detection (JAX x64-off silently downcasts int64 -> int32).
// Reading N_EDGES int32 words is in-bounds under BOTH interpretations; for
// int64 values < 100000 every odd (high) word is 0, so a nonzero odd word
// proves int32.
// ---------------------------------------------------------------------------
__global__ void reset_kernel() { g_flag = 0; }

__global__ void probe_dtype_kernel(const int* __restrict__ p32) {
    int i = blockIdx.x * blockDim.x + threadIdx.x;
    int w = 2 * i + 1;
    if (w < N_EDGES && p32[w] != 0) atomicExch(&g_flag, 1);
}

__global__ void zero_cnt_kernel() {
    int i = blockIdx.x * blockDim.x + threadIdx.x;
    if (i < N_NODES) g_cnt[i] = 0;
}

// Convert (dtype-branch + clamp) and histogram rows in one pass.
__global__ void convert_hist_kernel(const void* __restrict__ rptr,
                                    const void* __restrict__ cptr) {
    int e = blockIdx.x * blockDim.x + threadIdx.x;
    if (e >= N_EDGES) return;
    int r, c;
    if (g_flag == 1) {
        r = ((const int*)rptr)[e];
        c = ((const int*)cptr)[e];
    } else {
        r = (int)((const long long*)rptr)[e];
        c = (int)((const long long*)cptr)[e];
    }
    r = min(max(r, 0), N_NODES - 1);
    c = min(max(c, 0), N_NODES - 1);
    g_row[e] = r;
    g_col[e] = c;
    atomicAdd(&g_cnt[r], 1);
}

// ---------------------------------------------------------------------------
// Single-block exclusive scan of g_cnt -> g_rowptr (98 chunks of 1024).
// ---------------------------------------------------------------------------
__global__ void scan_kernel() {
    __shared__ int s_warp[32];
    int tid = threadIdx.x, lane = tid & 31, wid = tid >> 5;
    int carry = 0;
    for (int base = 0; base < N_NODES; base += 1024) {
        int i = base + tid;
        int v = (i < N_NODES) ? g_cnt[i] : 0;
        int s = v;
        #pragma unroll
        for (int off = 1; off < 32; off <<= 1) {
            int n = __shfl_up_sync(0xffffffffu, s, off);
            if (lane >= off) s += n;
        }
        if (lane == 31) s_warp[wid] = s;
        __syncthreads();
        if (wid == 0) {
            int ws = s_warp[lane];
            #pragma unroll
            for (int off = 1; off < 32; off <<= 1) {
                int n = __shfl_up_sync(0xffffffffu, ws, off);
                if (lane >= off) ws += n;
            }
            s_warp[lane] = ws;
        }
        __syncthreads();
        int woff = (wid > 0) ? s_warp[wid - 1] : 0;
        if (i < N_NODES) g_rowptr[i] = carry + woff + s - v;  // exclusive
        int tot = s_warp[31];
        __syncthreads();   // s_warp reused next chunk
        carry += tot;
    }
    if (tid == 0) g_rowptr[N_NODES] = carry;
}

__global__ void init_cursor_kernel() {
    int i = blockIdx.x * blockDim.x + threadIdx.x;
    if (i < N_NODES) g_cursor[i] = g_rowptr[i];
}

// Scatter edges into row-sorted order: one packed (val, col) per edge.
__global__ void place_edges_kernel(const float* __restrict__ vals) {
    int e = blockIdx.x * blockDim.x + threadIdx.x;
    if (e >= N_EDGES) return;
    int r = g_row[e];
    int pos = atomicAdd(&g_cursor[r], 1);
    g_edge[pos] = make_float2(vals[e], __int_as_float(g_col[e]));
}

// ---------------------------------------------------------------------------
// CSR-vector SpMM: one warp per row, lane f owns feature f (24 active).
// Edges are broadcast from the lane that loaded them via 2 shuffles; the
// inner 32-trip loop is fixed/unrolled so the 32 gathers batch (high MLP).
// Padding lanes carry v=0, c=0 -> dummy loads hit the L1-resident row 0.
// No atomics; each output element written exactly once.
// ---------------------------------------------------------------------------
__global__ void __launch_bounds__(256)
spmm_csr_kernel(const float* __restrict__ src, float* __restrict__ dst) {
    int w    = (blockIdx.x * blockDim.x + threadIdx.x) >> 5;  // row
    int lane = threadIdx.x & 31;
    if (w >= N_NODES) return;

    int start = g_rowptr[w];
    int end   = g_rowptr[w + 1];
    int f     = (lane < N_FEAT) ? lane : 0;

    float acc = 0.f;
    for (int base = start; base < end; base += 32) {
        int e = base + lane;
        float mv = 0.f;
        int   mc = 0;
        if (e < end) {
            float2 ed = g_edge[e];
            mv = ed.x;
            mc = __float_as_int(ed.y);
        }
        #pragma unroll
        for (int j = 0; j < 32; j++) {
            float v = __shfl_sync(0xffffffffu, mv, j);
            int   c = __shfl_sync(0xffffffffu, mc, j);
            acc = fmaf(v, __ldg(src + c * N_FEAT + f), acc);
        }
    }
    if (lane < N_FEAT) dst[w * N_FEAT + f] = acc;
}

// ---------------------------------------------------------------------------
// kernel_launch: detect dtype, build CSR once, then 6 atomic-free SpMMs.
// Default stream only, no syncs, no allocations -> graph-capturable.
// ---------------------------------------------------------------------------
extern "C" void kernel_launch(void* const* d_in, const int* in_sizes, int n_in,
                              void* d_out, int out_size) {
    const float* x    = (const float*)d_in[0];  // [N_NODES, N_FEAT]
    const float* vals = (const float*)d_in[1];  // [N_EDGES]
    const void*  rraw = d_in[2];                // [N_EDGES] int32 or int64
    const void*  craw = d_in[3];                // [N_EDGES] int32 or int64
    float* out = (float*)d_out;                 // [N_NODES, N_FEAT]

    float* bufA;
    float* bufB;
    cudaGetSymbolAddress((void**)&bufA, g_bufA);
    cudaGetSymbolAddress((void**)&bufB, g_bufB);

    const int threads = 256;
    const int eblocks = (N_EDGES + threads - 1) / threads;
    const int pblocks = (N_EDGES / 2 + threads - 1) / threads;
    const int nblocks = (N_NODES + threads - 1) / threads;
    const int sblocks = (N_NODES * 32 + threads - 1) / threads;  // warp per row

    // --- CSR build (once per launch) ---
    reset_kernel<<<1, 1>>>();
    probe_dtype_kernel<<<pblocks, threads>>>((const int*)rraw);
    zero_cnt_kernel<<<nblocks, threads>>>();
    convert_hist_kernel<<<eblocks, threads>>>(rraw, craw);
    scan_kernel<<<1, 1024>>>();
    init_cursor_kernel<<<nblocks, threads>>>();
    place_edges_kernel<<<eblocks, threads>>>(vals);

    // --- 6 layers, ping-pong: x -> A -> B -> A -> B -> A -> out ---
    const float* src[LAYERS] = { x, bufA, bufB, bufA, bufB, bufA };
    float*       dst[LAYERS] = { bufA, bufB, bufA, bufB, bufA, out };

    for (int l = 0; l < LAYERS; l++) {
        spmm_csr_kernel<<<sblocks, threads>>>(src[l], dst[l]);
    }
}

// round 5
// speedup vs baseline: 1.2597x; 1.0549x over previous
#include <cuda_runtime.h>
#include <cstdint>

#define N_NODES 100000
#define N_EDGES 3200000
#define N_FEAT  24
#define LAYERS  6
#define ROWS_PER_BLOCK 8
#define EDGE_CAP 2048   // smem edge window per block (8 rows, mean 256 edges)

// ---------------------------------------------------------------------------
// Scratch (allocation-free rule: __device__ globals).
// ---------------------------------------------------------------------------
__device__ __align__(16) float  g_bufA[(size_t)N_NODES * N_FEAT];
__device__ __align__(16) float  g_bufB[(size_t)N_NODES * N_FEAT];
__device__ __align__(16) int    g_row[N_EDGES];
__device__ __align__(16) int    g_col[N_EDGES];
__device__ __align__(16) float2 g_edge[N_EDGES];       // (val, col bits), row-sorted
__device__ int g_cnt[N_NODES];
__device__ int g_rowptr[N_NODES + 1];
__device__ int g_cursor[N_NODES];
// Static-init 0; replay-stable without a reset kernel: int32 inputs -> probe
// writes 1 every run (idempotent); int64 inputs -> never written, stays 0.
__device__ int g_flag = 0;

// ---------------------------------------------------------------------------
// Index dtype detection (JAX x64-off silently downcasts int64 -> int32).
// Reading N_EDGES int32 words is in-bounds under BOTH interpretations; for
// int64 values < 100000 every odd (high) word is 0, so a nonzero odd word
// proves int32.
// ---------------------------------------------------------------------------
__global__ void probe_dtype_kernel(const int* __restrict__ p32) {
    int i = blockIdx.x * blockDim.x + threadIdx.x;
    int w = 2 * i + 1;
    if (w < N_EDGES && p32[w] != 0) atomicExch(&g_flag, 1);
}

__global__ void zero_cnt_kernel() {
    int i = blockIdx.x * blockDim.x + threadIdx.x;
    if (i < N_NODES) g_cnt[i] = 0;
}

// Convert (dtype-branch + clamp) and histogram rows in one pass.
__global__ void convert_hist_kernel(const void* __restrict__ rptr,
                                    const void* __restrict__ cptr) {
    int e = blockIdx.x * blockDim.x + threadIdx.x;
    if (e >= N_EDGES) return;
    int r, c;
    if (g_flag == 1) {
        r = ((const int*)rptr)[e];
        c = ((const int*)cptr)[e];
    } else {
        r = (int)((const long long*)rptr)[e];
        c = (int)((const long long*)cptr)[e];
    }
    r = min(max(r, 0), N_NODES - 1);
    c = min(max(c, 0), N_NODES - 1);
    g_row[e] = r;
    g_col[e] = c;
    atomicAdd(&g_cnt[r], 1);
}

// ---------------------------------------------------------------------------
// Single-block exclusive scan of g_cnt -> g_rowptr AND g_cursor (fused).
// ---------------------------------------------------------------------------
__global__ void scan_kernel() {
    __shared__ int s_warp[32];
    int tid = threadIdx.x, lane = tid & 31, wid = tid >> 5;
    int carry = 0;
    for (int base = 0; base < N_NODES; base += 1024) {
        int i = base + tid;
        int v = (i < N_NODES) ? g_cnt[i] : 0;
        int s = v;
        #pragma unroll
        for (int off = 1; off < 32; off <<= 1) {
            int n = __shfl_up_sync(0xffffffffu, s, off);
            if (lane >= off) s += n;
        }
        if (lane == 31) s_warp[wid] = s;
        __syncthreads();
        if (wid == 0) {
            int ws = s_warp[lane];
            #pragma unroll
            for (int off = 1; off < 32; off <<= 1) {
                int n = __shfl_up_sync(0xffffffffu, ws, off);
                if (lane >= off) ws += n;
            }
            s_warp[lane] = ws;
        }
        __syncthreads();
        int woff = (wid > 0) ? s_warp[wid - 1] : 0;
        if (i < N_NODES) {
            int excl = carry + woff + s - v;
            g_rowptr[i] = excl;
            g_cursor[i] = excl;
        }
        int tot = s_warp[31];
        __syncthreads();   // s_warp reused next chunk
        carry += tot;
    }
    if (tid == 0) g_rowptr[N_NODES] = carry;
}

// Scatter edges into row-sorted order: one packed (val, col) per edge.
__global__ void place_edges_kernel(const float* __restrict__ vals) {
    int e = blockIdx.x * blockDim.x + threadIdx.x;
    if (e >= N_EDGES) return;
    int r = g_row[e];
    int pos = atomicAdd(&g_cursor[r], 1);
    g_edge[pos] = make_float2(vals[e], __int_as_float(g_col[e]));
}

// ---------------------------------------------------------------------------
// CSR SpMM: block = 8 warps = 8 consecutive rows. The 8 rows' edges are
// CONTIGUOUS in g_edge -> one coalesced cooperative copy into smem; warps
// then read edges via LDS broadcast (no shuffles). Lane f owns feature f
// (24 active). Unroll-4 with 4 accumulators: 4 independent gathers in
// flight, FMA chain cut 4x. No atomics; each output written exactly once.
// ---------------------------------------------------------------------------
__global__ void __launch_bounds__(256)
spmm_csr_kernel(const float* __restrict__ src, float* __restrict__ dst) {
    __shared__ float2 s_edge[EDGE_CAP];
    int tid  = threadIdx.x;
    int lane = tid & 31;
    int warp = tid >> 5;
    int rbase = blockIdx.x * ROWS_PER_BLOCK;

    int gstart = g_rowptr[rbase];
    int gend   = g_rowptr[rbase + ROWS_PER_BLOCK];
    int cnt    = gend - gstart;

    int ncopy = min(cnt, EDGE_CAP);
    for (int i = tid; i < ncopy; i += 256)
        s_edge[i] = g_edge[gstart + i];
    __syncthreads();

    int r     = rbase + warp;
    int start = g_rowptr[r]     - gstart;
    int end   = g_rowptr[r + 1] - gstart;
    int f     = (lane < N_FEAT) ? lane : 0;

    float a0 = 0.f, a1 = 0.f, a2 = 0.f, a3 = 0.f;
    int e = start;
    if (cnt <= EDGE_CAP) {
        for (; e + 4 <= end; e += 4) {
            float2 e0 = s_edge[e], e1 = s_edge[e + 1];
            float2 e2 = s_edge[e + 2], e3 = s_edge[e + 3];
            a0 = fmaf(e0.x, __ldg(src + __float_as_int(e0.y) * N_FEAT + f), a0);
            a1 = fmaf(e1.x, __ldg(src + __float_as_int(e1.y) * N_FEAT + f), a1);
            a2 = fmaf(e2.x, __ldg(src + __float_as_int(e2.y) * N_FEAT + f), a2);
            a3 = fmaf(e3.x, __ldg(src + __float_as_int(e3.y) * N_FEAT + f), a3);
        }
        for (; e < end; e++) {
            float2 ed = s_edge[e];
            a0 = fmaf(ed.x, __ldg(src + __float_as_int(ed.y) * N_FEAT + f), a0);
        }
    } else {
        // Astronomically rare overflow fallback: edges straight from global.
        const float2* ep = g_edge + gstart;
        for (; e + 4 <= end; e += 4) {
            float2 e0 = ep[e], e1 = ep[e + 1], e2 = ep[e + 2], e3 = ep[e + 3];
            a0 = fmaf(e0.x, __ldg(src + __float_as_int(e0.y) * N_FEAT + f), a0);
            a1 = fmaf(e1.x, __ldg(src + __float_as_int(e1.y) * N_FEAT + f), a1);
            a2 = fmaf(e2.x, __ldg(src + __float_as_int(e2.y) * N_FEAT + f), a2);
            a3 = fmaf(e3.x, __ldg(src + __float_as_int(e3.y) * N_FEAT + f), a3);
        }
        for (; e < end; e++) {
            float2 ed = ep[e];
            a0 = fmaf(ed.x, __ldg(src + __float_as_int(ed.y) * N_FEAT + f), a0);
        }
    }

    float acc = (a0 + a1) + (a2 + a3);
    if (lane < N_FEAT) dst[r * N_FEAT + f] = acc;
}

// ---------------------------------------------------------------------------
// kernel_launch: build CSR once (5 launches -> first SpMM is launch #6, the
// one ncu -s 5 -c 1 captures), then 6 atomic-free SpMMs. Default stream,
// no syncs, no allocations -> graph-capturable.
// ---------------------------------------------------------------------------
extern "C" void kernel_launch(void* const* d_in, const int* in_sizes, int n_in,
                              void* d_out, int out_size) {
    const float* x    = (const float*)d_in[0];  // [N_NODES, N_FEAT]
    const float* vals = (const float*)d_in[1];  // [N_EDGES]
    const void*  rraw = d_in[2];                // [N_EDGES] int32 or int64
    const void*  craw = d_in[3];                // [N_EDGES] int32 or int64
    float* out = (float*)d_out;                 // [N_NODES, N_FEAT]

    float* bufA;
    float* bufB;
    cudaGetSymbolAddress((void**)&bufA, g_bufA);
    cudaGetSymbolAddress((void**)&bufB, g_bufB);

    const int threads = 256;
    const int eblocks = (N_EDGES + threads - 1) / threads;
    const int pblocks = (N_EDGES / 2 + threads - 1) / threads;
    const int nblocks = (N_NODES + threads - 1) / threads;
    const int sblocks = N_NODES / ROWS_PER_BLOCK;  // 12500, exact

    // --- CSR build: launches #1..#5 ---
    probe_dtype_kernel<<<pblocks, threads>>>((const int*)rraw);
    zero_cnt_kernel<<<nblocks, threads>>>();
    convert_hist_kernel<<<eblocks, threads>>>(rraw, craw);
    scan_kernel<<<1, 1024>>>();
    place_edges_kernel<<<eblocks, threads>>>(vals);

    // --- 6 layers, ping-pong: x -> A -> B -> A -> B -> A -> out ---
    const float* src[LAYERS] = { x, bufA, bufB, bufA, bufB, bufA };
    float*       dst[LAYERS] = { bufA, bufB, bufA, bufB, bufA, out };

    for (int l = 0; l < LAYERS; l++) {
        spmm_csr_kernel<<<sblocks, threads>>>(src[l], dst[l]);
    }
}

// round 6
// speedup vs baseline: 1.3016x; 1.0333x over previous
#include <cuda_runtime.h>
#include <cstdint>

#define N_NODES 100000
#define N_EDGES 3200000
#define N_FEAT  24
#define LAYERS  6
#define SCAN_BLOCKS 98          // ceil(100000 / 1024)

// ---------------------------------------------------------------------------
// Scratch (allocation-free rule: __device__ globals).
// ---------------------------------------------------------------------------
__device__ __align__(16) float  g_bufA[(size_t)N_NODES * N_FEAT];
__device__ __align__(16) float  g_bufB[(size_t)N_NODES * N_FEAT];
__device__ __align__(16) float2 g_edge[N_EDGES];   // (val, col*96 as int bits), row-sorted
__device__ int g_cnt[N_NODES];
__device__ int g_rowptr[N_NODES + 1];
__device__ int g_cursor[N_NODES];
__device__ int g_bsum[SCAN_BLOCKS];
__device__ int g_boff[SCAN_BLOCKS];
// Static-init 0; replay-stable: int32 inputs -> probe writes 1 every run
// (idempotent); int64 inputs -> never written, stays 0.
__device__ int g_flag = 0;

// ---------------------------------------------------------------------------
// Index dtype detection (JAX x64-off silently downcasts int64 -> int32).
// Reading N_EDGES int32 words is in-bounds under BOTH interpretations; for
// int64 values < 100000 every odd (high) word is 0, so a nonzero odd word
// proves int32.
// ---------------------------------------------------------------------------
__global__ void probe_dtype_kernel(const int* __restrict__ p32) {
    int i = blockIdx.x * blockDim.x + threadIdx.x;
    int w = 2 * i + 1;
    if (w < N_EDGES && p32[w] != 0) atomicExch(&g_flag, 1);
}

__global__ void zero_cnt_kernel() {
    int i = blockIdx.x * blockDim.x + threadIdx.x;
    if (i < N_NODES) g_cnt[i] = 0;
}

__device__ __forceinline__ int load_idx(const void* p, int e) {
    int v = (g_flag == 1) ? ((const int*)p)[e] : (int)((const long long*)p)[e];
    return min(max(v, 0), N_NODES - 1);   // fault guard
}

// Histogram of row indices (no staging arrays; raw re-read in place pass).
__global__ void hist_kernel(const void* __restrict__ rptr) {
    int e = blockIdx.x * blockDim.x + threadIdx.x;
    if (e >= N_EDGES) return;
    atomicAdd(&g_cnt[load_idx(rptr, e)], 1);
}

// ---------------------------------------------------------------------------
// Parallel exclusive scan of g_cnt -> g_rowptr (+cursor), 3 phases.
// ---------------------------------------------------------------------------
__global__ void scan_local_kernel() {   // 98 blocks x 1024
    __shared__ int s_w[32];
    int tid = threadIdx.x, lane = tid & 31, wid = tid >> 5;
    int i = blockIdx.x * 1024 + tid;
    int v = (i < N_NODES) ? g_cnt[i] : 0;
    int s = v;
    #pragma unroll
    for (int off = 1; off < 32; off <<= 1) {
        int n = __shfl_up_sync(0xffffffffu, s, off);
        if (lane >= off) s += n;
    }
    if (lane == 31) s_w[wid] = s;
    __syncthreads();
    if (wid == 0) {
        int ws = s_w[lane];
        #pragma unroll
        for (int off = 1; off < 32; off <<= 1) {
            int n = __shfl_up_sync(0xffffffffu, ws, off);
            if (lane >= off) ws += n;
        }
        s_w[lane] = ws;
    }
    __syncthreads();
    int woff = (wid > 0) ? s_w[wid - 1] : 0;
    if (i < N_NODES) g_rowptr[i] = woff + s - v;   // block-local exclusive
    if (tid == 1023) g_bsum[blockIdx.x] = s_w[31]; // block total
}

__global__ void scan_sums_kernel() {    // 1 block x 128 (98 sums)
    __shared__ int s_w[4];
    int tid = threadIdx.x, lane = tid & 31, wid = tid >> 5;
    int v = (tid < SCAN_BLOCKS) ? g_bsum[tid] : 0;
    int s = v;
    #pragma unroll
    for (int off = 1; off < 32; off <<= 1) {
        int n = __shfl_up_sync(0xffffffffu, s, off);
        if (lane >= off) s += n;
    }
    if (lane == 31) s_w[wid] = s;
    __syncthreads();
    if (tid == 0) {
        int a = 0;
        #pragma unroll
        for (int k = 0; k < 4; k++) { int t = s_w[k]; s_w[k] = a; a += t; }
        g_rowptr[N_NODES] = a;          // grand total (= N_EDGES)
    }
    __syncthreads();
    if (tid < SCAN_BLOCKS) g_boff[tid] = s_w[wid] + s - v;  // exclusive
}

__global__ void scan_add_kernel() {     // 98 blocks x 1024
    int i = blockIdx.x * 1024 + threadIdx.x;
    if (i < N_NODES) {
        int r = g_rowptr[i] + g_boff[blockIdx.x];
        g_rowptr[i] = r;
        g_cursor[i] = r;
    }
}

// ---------------------------------------------------------------------------
// Scatter edges into row-sorted order. Payload = (val, col*96): col pre-scaled
// to a byte offset so the SpMM gather is a single add off a per-lane base.
// ---------------------------------------------------------------------------
__global__ void place_edges_kernel(const void* __restrict__ rptr,
                                   const void* __restrict__ cptr,
                                   const float* __restrict__ vals) {
    int e = blockIdx.x * blockDim.x + threadIdx.x;
    if (e >= N_EDGES) return;
    int r = load_idx(rptr, e);
    int c = load_idx(cptr, e);
    int pos = atomicAdd(&g_cursor[r], 1);
    g_edge[pos] = make_float2(vals[e], __int_as_float(c * (N_FEAT * 4)));
}

// ---------------------------------------------------------------------------
// CSR SpMM: one warp per row, lane f owns feature f (24 active; lanes 24-31
// duplicate f=0). Edges streamed directly from g_edge with warp-uniform
// LDG.64 — row-sorted order means consecutive edges share 128B lines and
// L1-hit after the first. Unroll-8, 8 accumulators -> 8 in-flight gathers
// per warp. Gather address = per-lane base + prescaled byte offset (1 add).
// No atomics; each output written exactly once.
// ---------------------------------------------------------------------------
__global__ void __launch_bounds__(256)
spmm_csr_kernel(const float* __restrict__ src, float* __restrict__ dst) {
    int w    = (blockIdx.x * blockDim.x + threadIdx.x) >> 5;  // row
    int lane = threadIdx.x & 31;

    int start = g_rowptr[w];
    int end   = g_rowptr[w + 1];
    int f     = (lane < N_FEAT) ? lane : 0;
    const char* sp = (const char*)src + f * 4;

    float a0 = 0.f, a1 = 0.f, a2 = 0.f, a3 = 0.f;
    float a4 = 0.f, a5 = 0.f, a6 = 0.f, a7 = 0.f;

    int e = start;
    for (; e + 8 <= end; e += 8) {
        float2 d0 = g_edge[e + 0];
        float2 d1 = g_edge[e + 1];
        float2 d2 = g_edge[e + 2];
        float2 d3 = g_edge[e + 3];
        float2 d4 = g_edge[e + 4];
        float2 d5 = g_edge[e + 5];
        float2 d6 = g_edge[e + 6];
        float2 d7 = g_edge[e + 7];
        a0 = fmaf(d0.x, *(const float*)(sp + __float_as_int(d0.y)), a0);
        a1 = fmaf(d1.x, *(const float*)(sp + __float_as_int(d1.y)), a1);
        a2 = fmaf(d2.x, *(const float*)(sp + __float_as_int(d2.y)), a2);
        a3 = fmaf(d3.x, *(const float*)(sp + __float_as_int(d3.y)), a3);
        a4 = fmaf(d4.x, *(const float*)(sp + __float_as_int(d4.y)), a4);
        a5 = fmaf(d5.x, *(const float*)(sp + __float_as_int(d5.y)), a5);
        a6 = fmaf(d6.x, *(const float*)(sp + __float_as_int(d6.y)), a6);
        a7 = fmaf(d7.x, *(const float*)(sp + __float_as_int(d7.y)), a7);
    }
    for (; e < end; e++) {
        float2 d = g_edge[e];
        a0 = fmaf(d.x, *(const float*)(sp + __float_as_int(d.y)), a0);
    }

    float acc = ((a0 + a1) + (a2 + a3)) + ((a4 + a5) + (a6 + a7));
    if (lane < N_FEAT) dst[w * N_FEAT + lane] = acc;
}

// ---------------------------------------------------------------------------
// kernel_launch: build CSR (7 launches), then 6 atomic-free SpMMs.
// Default stream, no syncs, no allocations -> graph-capturable.
// ---------------------------------------------------------------------------
extern "C" void kernel_launch(void* const* d_in, const int* in_sizes, int n_in,
                              void* d_out, int out_size) {
    const float* x    = (const float*)d_in[0];  // [N_NODES, N_FEAT]
    const float* vals = (const float*)d_in[1];  // [N_EDGES]
    const void*  rraw = d_in[2];                // [N_EDGES] int32 or int64
    const void*  craw = d_in[3];                // [N_EDGES] int32 or int64
    float* out = (float*)d_out;                 // [N_NODES, N_FEAT]

    float* bufA;
    float* bufB;
    cudaGetSymbolAddress((void**)&bufA, g_bufA);
    cudaGetSymbolAddress((void**)&bufB, g_bufB);

    const int threads = 256;
    const int eblocks = (N_EDGES + threads - 1) / threads;      // 12500
    const int pblocks = (N_EDGES / 2 + threads - 1) / threads;  // 6250
    const int nblocks = (N_NODES + threads - 1) / threads;      // 391
    const int sblocks = N_NODES / 8;                            // 12500 (warp/row)

    // --- CSR build ---
    probe_dtype_kernel<<<pblocks, threads>>>((const int*)rraw);
    zero_cnt_kernel<<<nblocks, threads>>>();
    hist_kernel<<<eblocks, threads>>>(rraw);
    scan_local_kernel<<<SCAN_BLOCKS, 1024>>>();
    scan_sums_kernel<<<1, 128>>>();
    scan_add_kernel<<<SCAN_BLOCKS, 1024>>>();
    place_edges_kernel<<<eblocks, threads>>>(rraw, craw, vals);

    // --- 6 layers, ping-pong: x -> A -> B -> A -> B -> A -> out ---
    const float* src[LAYERS] = { x, bufA, bufB, bufA, bufB, bufA };
    float*       dst[LAYERS] = { bufA, bufB, bufA, bufB, bufA, out };

    for (int l = 0; l < LAYERS; l++) {
        spmm_csr_kernel<<<sblocks, threads>>>(src[l], dst[l]);
    }
}

// round 7
// speedup vs baseline: 4.4449x; 3.4148x over previous
#include <cuda_runtime.h>
#include <cstdint>

#define N_NODES 100000
#define N_EDGES 3200000
#define N_FEAT  24
#define LAYERS  6
#define BUILD_BLOCKS  148
#define BUILD_THREADS 1024
#define CHUNK 676            // ceil(N_NODES / BUILD_BLOCKS)

// ---------------------------------------------------------------------------
// Scratch (allocation-free rule: __device__ globals).
// g_edge padded by 8 zero entries: SpMM reads full 8-edge batches past row
// ends; pad entries are never written (place covers [0,N_EDGES) exactly),
// so their (val=0, off=0) contributes nothing and addresses stay in-bounds.
// ---------------------------------------------------------------------------
__device__ __align__(16) float  g_bufA[(size_t)N_NODES * N_FEAT];
__device__ __align__(16) float  g_bufB[(size_t)N_NODES * N_FEAT];
__device__ __align__(16) float2 g_edge[N_EDGES + 8];   // (val, col*96 bits), row-sorted
__device__ int g_cnt[N_NODES];
__device__ int g_rowptr[N_NODES + 1];
__device__ int g_cursor[N_NODES];
__device__ int g_bsum[BUILD_BLOCKS];
__device__ int g_boff[BUILD_BLOCKS];
// Monotone: int32 inputs -> set to 1 every run (idempotent); int64 -> stays 0.
__device__ int g_flag = 0;
// Monotone ticket barrier counter; never reset -> replay-safe.
__device__ unsigned g_bar = 0;

// ---------------------------------------------------------------------------
// Software grid barrier for the persistent build kernel. All BUILD_BLOCKS
// blocks are co-resident (148 blocks <= 148 SMs, wave 1), so spinning is
// deadlock-free. Ticket-relative target keeps it correct across graph
// replays without resets.
// ---------------------------------------------------------------------------
__device__ __forceinline__ void grid_barrier() {
    __syncthreads();
    if (threadIdx.x == 0) {
        __threadfence();
        unsigned ticket = atomicAdd(&g_bar, 1u);
        unsigned target = (ticket / BUILD_BLOCKS + 1u) * BUILD_BLOCKS;
        unsigned v;
        do {
            asm volatile("ld.global.acquire.gpu.u32 %0, [%1];"
                         : "=r"(v) : "l"(&g_bar));
            if (v < target) __nanosleep(64);
        } while (v < target);
    }
    __syncthreads();
}

__device__ __forceinline__ int load_idx(const void* p, int e, int flag) {
    int v = (flag == 1) ? ((const int*)p)[e] : (int)((const long long*)p)[e];
    return min(max(v, 0), N_NODES - 1);   // fault guard
}

// ---------------------------------------------------------------------------
// Persistent single-launch CSR build:
//   phase 0: zero g_cnt + dtype probe (JAX x64-off downcasts int64->int32;
//            odd int32 words are all-zero iff the buffer is int64)
//   phase 1: row histogram
//   phase 2: 3-step exclusive scan -> g_rowptr, g_cursor
//   phase 3: scatter (val, col*96) into row-sorted g_edge
// ---------------------------------------------------------------------------
__global__ void __launch_bounds__(BUILD_THREADS)
build_csr_kernel(const void* __restrict__ rptr,
                 const void* __restrict__ cptr,
                 const float* __restrict__ vals) {
    const int tid    = threadIdx.x;
    const int gid    = blockIdx.x * BUILD_THREADS + tid;
    const int stride = BUILD_BLOCKS * BUILD_THREADS;

    // --- phase 0: zero counts + probe dtype ---
    for (int i = gid; i < N_NODES; i += stride) g_cnt[i] = 0;
    const int* p32 = (const int*)rptr;
    for (int i = gid; i < N_EDGES / 2; i += stride)
        if (p32[2 * i + 1] != 0) g_flag = 1;
    grid_barrier();

    const int flag = g_flag;

    // --- phase 1: histogram ---
    for (int e = gid; e < N_EDGES; e += stride)
        atomicAdd(&g_cnt[load_idx(rptr, e, flag)], 1);
    grid_barrier();

    // --- phase 2a: block-local exclusive scan of a contiguous CHUNK ---
    {
        __shared__ int s_w[32];
        int lane = tid & 31, wid = tid >> 5;
        int i = blockIdx.x * CHUNK + tid;
        int v = (tid < CHUNK && i < N_NODES) ? g_cnt[i] : 0;
        int s = v;
        #pragma unroll
        for (int off = 1; off < 32; off <<= 1) {
            int n = __shfl_up_sync(0xffffffffu, s, off);
            if (lane >= off) s += n;
        }
        if (lane == 31) s_w[wid] = s;
        __syncthreads();
        if (wid == 0) {
            int ws = s_w[lane];
            #pragma unroll
            for (int off = 1; off < 32; off <<= 1) {
                int n = __shfl_up_sync(0xffffffffu, ws, off);
                if (lane >= off) ws += n;
            }
            s_w[lane] = ws;
        }
        __syncthreads();
        int woff = (wid > 0) ? s_w[wid - 1] : 0;
        if (tid < CHUNK && i < N_NODES) g_rowptr[i] = woff + s - v;  // local excl
        if (tid == BUILD_THREADS - 1) g_bsum[blockIdx.x] = s_w[31];
    }
    grid_barrier();

    // --- phase 2b: block 0 scans the 148 block sums (Hillis-Steele) ---
    {
        __shared__ int sb[BUILD_BLOCKS];
        if (blockIdx.x == 0) {
            if (tid < BUILD_BLOCKS) sb[tid] = g_bsum[tid];
            __syncthreads();
            for (int off = 1; off < BUILD_BLOCKS; off <<= 1) {
                int t = (tid < BUILD_BLOCKS && tid >= off) ? sb[tid - off] : 0;
                __syncthreads();
                if (tid < BUILD_BLOCKS) sb[tid] += t;
                __syncthreads();
            }
            if (tid < BUILD_BLOCKS) g_boff[tid] = sb[tid] - g_bsum[tid];
            if (tid == BUILD_BLOCKS - 1) g_rowptr[N_NODES] = sb[BUILD_BLOCKS - 1];
        } else {
            // keep __syncthreads counts per-block uniform (they're block-scoped;
            // nothing needed here)
        }
    }
    grid_barrier();

    // --- phase 2c: add block offsets; init cursors ---
    for (int i = gid; i < N_NODES; i += stride) {
        int r = g_rowptr[i] + g_boff[i / CHUNK];
        g_rowptr[i] = r;
        g_cursor[i] = r;
    }
    grid_barrier();

    // --- phase 3: place edges (payload: val, col*96 byte offset) ---
    for (int e = gid; e < N_EDGES; e += stride) {
        int r = load_idx(rptr, e, flag);
        int c = load_idx(cptr, e, flag);
        int pos = atomicAdd(&g_cursor[r], 1);
        g_edge[pos] = make_float2(vals[e], __int_as_float(c * (N_FEAT * 4)));
    }
}

// ---------------------------------------------------------------------------
// CSR SpMM: one warp per row, lane f owns feature f (24 active; lanes 24-31
// duplicate f=0, merging into lane 0's sector). Edges stream as aligned
// float4 (2 edges per LDG.128, base rounded down to even index). Every
// iteration is a FULL masked 8-edge batch -- no serial remainder loop; edge
// validity is one unsigned range-compare + select per edge. 8 accumulators
// keep 8 gathers in flight. No atomics; each output written exactly once.
// ---------------------------------------------------------------------------
__global__ void __launch_bounds__(256)
spmm_csr_kernel(const float* __restrict__ src, float* __restrict__ dst) {
    int w    = (blockIdx.x * blockDim.x + threadIdx.x) >> 5;  // row
    int lane = threadIdx.x & 31;

    int start = g_rowptr[w];
    int end   = g_rowptr[w + 1];
    unsigned len = (unsigned)(end - start);
    int f = (lane < N_FEAT) ? lane : 0;
    const char* sp = (const char*)src + f * 4;

    float a0 = 0.f, a1 = 0.f, a2 = 0.f, a3 = 0.f;
    float a4 = 0.f, a5 = 0.f, a6 = 0.f, a7 = 0.f;

    int base = start & ~1;   // 16B-aligned float4 loads
    for (int e = base; e < end; e += 8) {
        float4 p0 = *(const float4*)&g_edge[e + 0];  // edges e,   e+1
        float4 p1 = *(const float4*)&g_edge[e + 2];  // edges e+2, e+3
        float4 p2 = *(const float4*)&g_edge[e + 4];
        float4 p3 = *(const float4*)&g_edge[e + 6];

        float v0 = ((unsigned)(e + 0 - start) < len) ? p0.x : 0.f;
        float v1 = ((unsigned)(e + 1 - start) < len) ? p0.z : 0.f;
        float v2 = ((unsigned)(e + 2 - start) < len) ? p1.x : 0.f;
        float v3 = ((unsigned)(e + 3 - start) < len) ? p1.z : 0.f;
        float v4 = ((unsigned)(e + 4 - start) < len) ? p2.x : 0.f;
        float v5 = ((unsigned)(e + 5 - start) < len) ? p2.z : 0.f;
        float v6 = ((unsigned)(e + 6 - start) < len) ? p3.x : 0.f;
        float v7 = ((unsigned)(e + 7 - start) < len) ? p3.z : 0.f;

        a0 = fmaf(v0, *(const float*)(sp + __float_as_int(p0.y)), a0);
        a1 = fmaf(v1, *(const float*)(sp + __float_as_int(p0.w)), a1);
        a2 = fmaf(v2, *(const float*)(sp + __float_as_int(p1.y)), a2);
        a3 = fmaf(v3, *(const float*)(sp + __float_as_int(p1.w)), a3);
        a4 = fmaf(v4, *(const float*)(sp + __float_as_int(p2.y)), a4);
        a5 = fmaf(v5, *(const float*)(sp + __float_as_int(p2.w)), a5);
        a6 = fmaf(v6, *(const float*)(sp + __float_as_int(p3.y)), a6);
        a7 = fmaf(v7, *(const float*)(sp + __float_as_int(p3.w)), a7);
    }

    float acc = ((a0 + a1) + (a2 + a3)) + ((a4 + a5) + (a6 + a7));
    if (lane < N_FEAT) dst[w * N_FEAT + lane] = acc;
}

// ---------------------------------------------------------------------------
// kernel_launch: ONE build launch, then 6 SpMMs (launch #4 = SpMM layer 3,
// which is what ncu captures). Default stream, no syncs, no allocations
// -> graph-capturable.
// ---------------------------------------------------------------------------
extern "C" void kernel_launch(void* const* d_in, const int* in_sizes, int n_in,
                              void* d_out, int out_size) {
    const float* x    = (const float*)d_in[0];  // [N_NODES, N_FEAT]
    const float* vals = (const float*)d_in[1];  // [N_EDGES]
    const void*  rraw = d_in[2];                // [N_EDGES] int32 or int64
    const void*  craw = d_in[3];                // [N_EDGES] int32 or int64
    float* out = (float*)d_out;                 // [N_NODES, N_FEAT]

    float* bufA;
    float* bufB;
    cudaGetSymbolAddress((void**)&bufA, g_bufA);
    cudaGetSymbolAddress((void**)&bufB, g_bufB);

    const int sblocks = N_NODES / 8;   // 12500 blocks, warp per row

    build_csr_kernel<<<BUILD_BLOCKS, BUILD_THREADS>>>(rraw, craw, vals);

    // 6 layers, ping-pong: x -> A -> B -> A -> B -> A -> out
    const float* src[LAYERS] = { x, bufA, bufB, bufA, bufB, bufA };
    float*       dst[LAYERS] = { bufA, bufB, bufA, bufB, bufA, out };

    for (int l = 0; l < LAYERS; l++) {
        spmm_csr_kernel<<<sblocks, 256>>>(src[l], dst[l]);
    }
}